// round 5
// baseline (speedup 1.0000x reference)
#include <cuda_runtime.h>
#include <math.h>
#include <float.h>

#define Bsz 16
#define Tsz 128
#define Hsz 512
#define Vsz 32000
#define STEPS 127
#define MR (STEPS*Bsz)   /* 2032 */
#define NB 128

/* ---------- device scratch ---------- */
__device__ float g_vt[Bsz*Tsz*Hsz];
__device__ float g_xe[MR*Hsz];
__device__ float g_gix[MR*3*Hsz];
__device__ float g_Hs[MR*Hsz];
__device__ float g_q[Bsz*Hsz];
__device__ float g_gh[Bsz*3*Hsz];
__device__ float g_scores[Bsz*Tsz];
__device__ float g_ctxT[Hsz*Bsz];
__device__ float g_hT[2*Hsz*Bsz];
__device__ volatile int g_flags[NB];
__device__ volatile int g_rel;

/* ---------- helpers ---------- */
__device__ __forceinline__ unsigned long long pk2(float lo, float hi){
    unsigned long long r; asm("mov.b64 %0,{%1,%2};" : "=l"(r) : "f"(lo), "f"(hi)); return r;
}
__device__ __forceinline__ void upk2(unsigned long long v, float& lo, float& hi){
    asm("mov.b64 {%0,%1},%2;" : "=f"(lo), "=f"(hi) : "l"(v));
}
__device__ __forceinline__ void fma2(unsigned long long& d, unsigned long long a, unsigned long long b){
    asm("fma.rn.f32x2 %0,%1,%2,%0;" : "+l"(d) : "l"(a), "l"(b));
}
__device__ __forceinline__ float wred(float v){
    v += __shfl_xor_sync(0xffffffffu, v, 16);
    v += __shfl_xor_sync(0xffffffffu, v, 8);
    v += __shfl_xor_sync(0xffffffffu, v, 4);
    v += __shfl_xor_sync(0xffffffffu, v, 2);
    v += __shfl_xor_sync(0xffffffffu, v, 1);
    return v;
}
__device__ __forceinline__ float sigf(float x){ return 1.0f/(1.0f+expf(-x)); }

/* ---------- init: h0 transpose + barrier reset ---------- */
__global__ void k_h0(const float* __restrict__ eh){
    int i = blockIdx.x*256 + threadIdx.x;           /* 8192 */
    if (i < Hsz*Bsz){
        int b = i >> 9, k = i & 511;
        g_hT[k*16 + b] = eh[i];
    }
    if (blockIdx.x == 0 && threadIdx.x < NB) g_flags[threadIdx.x] = 0;
    if (blockIdx.x == 0 && threadIdx.x == 0) g_rel = 0;
}

/* ---------- gather embeddings ---------- */
__global__ void k_gather(const float* __restrict__ emb, const int* __restrict__ tgt){
    int m = blockIdx.x;                 /* 0..2031, m = s*16+b */
    int s = m >> 4, b = m & 15;
    int tok = (s == 0) ? 1 : tgt[b*Tsz + s];
    const float4* src = (const float4*)(emb + (size_t)tok*Hsz);
    float4* dst = (float4*)(g_xe + (size_t)m*Hsz);
    for (int i = threadIdx.x; i < Hsz/4; i += blockDim.x) dst[i] = src[i];
}

/* ---------- zero out[:,0,:] ---------- */
__global__ void k_zero(float* __restrict__ out){
    int i = blockIdx.x*256 + threadIdx.x;           /* 512000 */
    int b = i / Vsz, v = i - b*Vsz;
    out[(size_t)b*Tsz*Vsz + v] = 0.0f;
}

/* ---------- hT tail ---------- */
__global__ void k_tail(float* __restrict__ out){
    int i = blockIdx.x*256 + threadIdx.x;           /* 8192 */
    int b = i >> 9, k = i & 511;
    out[(size_t)Bsz*Tsz*Vsz + i] = g_Hs[(size_t)((STEPS-1)*16 + b)*Hsz + k];
}

/* ---------- 128x128 fp32 GEMM: C = A @ B^T + bias (FFMA2) ---------- */
template<bool SCATTER>
__global__ void __launch_bounds__(256)
k_gemm128(const float* __restrict__ A, const float* __restrict__ B,
          const float* __restrict__ bias, float* __restrict__ C,
          int M, int ldb, int ldc)
{
    __shared__ float As[16][136];
    __shared__ float Bs[16][136];
    int tid = threadIdx.x;
    int tx = tid & 15, ty = tid >> 4;
    int n0 = blockIdx.x*128, m0 = blockIdx.y*128;
    int lr = tid >> 1, lq = (tid & 1)*8;

    unsigned long long acc[8][4];
    #pragma unroll
    for (int i = 0; i < 8; i++){
        #pragma unroll
        for (int j = 0; j < 4; j++) acc[i][j] = 0ull;
    }

    bool av = (m0 + lr) < M;
    const float* Arow = A + (size_t)(m0 + lr)*512 + lq;
    const float* Brow = B + (size_t)(n0 + lr)*ldb + lq;

    for (int k0 = 0; k0 < 512; k0 += 16){
        float4 a0, a1;
        if (av){ a0 = *(const float4*)(Arow + k0); a1 = *(const float4*)(Arow + k0 + 4); }
        else   { a0 = make_float4(0,0,0,0); a1 = a0; }
        float4 b0 = *(const float4*)(Brow + k0);
        float4 b1 = *(const float4*)(Brow + k0 + 4);
        __syncthreads();
        As[lq+0][lr]=a0.x; As[lq+1][lr]=a0.y; As[lq+2][lr]=a0.z; As[lq+3][lr]=a0.w;
        As[lq+4][lr]=a1.x; As[lq+5][lr]=a1.y; As[lq+6][lr]=a1.z; As[lq+7][lr]=a1.w;
        Bs[lq+0][lr]=b0.x; Bs[lq+1][lr]=b0.y; Bs[lq+2][lr]=b0.z; Bs[lq+3][lr]=b0.w;
        Bs[lq+4][lr]=b1.x; Bs[lq+5][lr]=b1.y; Bs[lq+6][lr]=b1.z; Bs[lq+7][lr]=b1.w;
        __syncthreads();
        #pragma unroll
        for (int kk = 0; kk < 16; kk++){
            float4 aA = *(const float4*)&As[kk][ty*8];
            float4 aB = *(const float4*)&As[kk][ty*8 + 4];
            ulonglong2 bp0 = *(const ulonglong2*)&Bs[kk][tx*8];
            ulonglong2 bp1 = *(const ulonglong2*)&Bs[kk][tx*8 + 4];
            float am[8] = {aA.x,aA.y,aA.z,aA.w,aB.x,aB.y,aB.z,aB.w};
            #pragma unroll
            for (int i = 0; i < 8; i++){
                unsigned long long ad = pk2(am[i], am[i]);
                fma2(acc[i][0], ad, bp0.x);
                fma2(acc[i][1], ad, bp0.y);
                fma2(acc[i][2], ad, bp1.x);
                fma2(acc[i][3], ad, bp1.y);
            }
        }
    }

    float bb[8];
    #pragma unroll
    for (int c = 0; c < 8; c++) bb[c] = __ldg(bias + n0 + tx*8 + c);

    #pragma unroll
    for (int i = 0; i < 8; i++){
        int row = m0 + ty*8 + i;
        if (row < M){
            float* dst;
            if (SCATTER){
                int b = row & 15, s = row >> 4;
                dst = C + (size_t)b*Tsz*Vsz + (size_t)(s+1)*Vsz + n0 + tx*8;
            } else {
                dst = C + (size_t)row*ldc + n0 + tx*8;
            }
            float4 r0, r1;
            upk2(acc[i][0], r0.x, r0.y); upk2(acc[i][1], r0.z, r0.w);
            upk2(acc[i][2], r1.x, r1.y); upk2(acc[i][3], r1.z, r1.w);
            r0.x += bb[0]; r0.y += bb[1]; r0.z += bb[2]; r0.w += bb[3];
            r1.x += bb[4]; r1.y += bb[5]; r1.z += bb[6]; r1.w += bb[7];
            *(float4*)dst = r0; *(float4*)(dst+4) = r1;
        }
    }
}

/* ---------- persistent recurrence ---------- */
__device__ __forceinline__ void gbar(int p){
    __syncthreads();
    if (blockIdx.x == 0 && threadIdx.x < 32){
        if (threadIdx.x == 0){ __threadfence(); g_flags[0] = p; }
        for (int i = threadIdx.x; i < NB; i += 32){ while (g_flags[i] < p) {} }
        __syncwarp();
        if (threadIdx.x == 0){ __threadfence(); g_rel = p; }
    } else if (threadIdx.x == 0){
        __threadfence();
        g_flags[blockIdx.x] = p;
        while (g_rel < p) {}
        __threadfence();
    }
    __syncthreads();
}

__device__ __forceinline__ void stageSH(float* SH, const float* src){
    __syncthreads();
    for (int i = threadIdx.x; i < Hsz*Bsz; i += 256)
        SH[(i>>4)*17 + (i&15)] = __ldcg(src + i);
    __syncthreads();
}

/* warp: 2 rows x 16 batches, K=512; SH = rhs [k][b] pad17 */
__device__ __forceinline__ void bgemm2(const float* __restrict__ w0r, const float* __restrict__ w1r,
                                       float bias0, float bias1,
                                       float* o0, float* o1, int st,
                                       const float* SH, int lane)
{
    float a0[16], a1[16];
    #pragma unroll
    for (int b = 0; b < 16; b++){ a0[b]=0.f; a1[b]=0.f; }
    #pragma unroll 4
    for (int ki = 0; ki < 16; ki++){
        int k = ki*32 + lane;
        float w0 = __ldg(w0r + k), w1 = __ldg(w1r + k);
        #pragma unroll
        for (int b = 0; b < 16; b++){
            float hv = SH[k*17 + b];
            a0[b] = fmaf(w0, hv, a0[b]);
            a1[b] = fmaf(w1, hv, a1[b]);
        }
    }
    #pragma unroll
    for (int b = 0; b < 16; b++){
        float v0 = wred(a0[b]);
        float v1 = wred(a1[b]);
        if (lane == b){
            __stcg(o0 + b*st, v0 + bias0);
            __stcg(o1 + b*st, v1 + bias1);
        }
    }
}

__global__ void __launch_bounds__(256)
k_recur(const float* __restrict__ enc, const int* __restrict__ mask,
        const float* __restrict__ Wq,  const float* __restrict__ bq,
        const float* __restrict__ Whh, const float* __restrict__ bhh,
        const float* __restrict__ Wih, const float* __restrict__ Wc,
        const float* __restrict__ bc)
{
    __shared__ float SH[Hsz*17];
    int tid = threadIdx.x;
    int lane = tid & 31;
    int wg = blockIdx.x*8 + (tid >> 5);        /* 0..1023 */
    float bcv = __ldg(bc);
    int p = 0;

    for (int s = 0; s < STEPS; s++){
        /* ---- phase A: q = h@Wq^T+bq ; gh = h@Whh^T+bhh ---- */
        stageSH(SH, g_hT + (s&1)*(Hsz*Bsz));
        {
            int r0 = 2*wg;
            if (r0 < 512){
                bgemm2(Wq + (size_t)r0*512, Wq + (size_t)(r0+1)*512,
                       __ldg(bq+r0), __ldg(bq+r0+1),
                       g_q + r0, g_q + r0 + 1, 512, SH, lane);
            } else {
                int g = r0 - 512;
                bgemm2(Whh + (size_t)g*512, Whh + (size_t)(g+1)*512,
                       __ldg(bhh+g), __ldg(bhh+g+1),
                       g_gh + g, g_gh + g + 1, 1536, SH, lane);
            }
        }
        gbar(++p);

        /* ---- phase B: scores ---- */
        #pragma unroll
        for (int i = 0; i < 2; i++){
            int pr = 2*wg + i;
            int b = pr >> 7, t = pr & 127;
            const float* vp = g_vt + ((size_t)b*Tsz + t)*Hsz;
            const float* qp = g_q + b*Hsz;
            float acc = 0.f;
            #pragma unroll 4
            for (int ki = 0; ki < 16; ki++){
                int k = ki*32 + lane;
                acc += __ldg(Wc + k) * tanhf(__ldcg(qp + k) + __ldg(vp + k));
            }
            acc = wred(acc);
            if (lane == 0){
                float sc = acc + bcv;
                if (__ldg(mask + b*Tsz + t) == 0) sc = -FLT_MAX;
                __stcg(g_scores + b*Tsz + t, sc);
            }
        }
        gbar(++p);

        /* ---- phase C: softmax + ctx (CTA = (b, 64-dim chunk)) ---- */
        {
            int b = blockIdx.x >> 3, ch = blockIdx.x & 7, hb = ch*64;
            __syncthreads();
            if (tid < 128) SH[tid] = __ldcg(g_scores + b*Tsz + tid);
            __syncthreads();
            if (tid == 0){
                float mx = -FLT_MAX;
                for (int i = 0; i < 128; i++) mx = fmaxf(mx, SH[i]);
                float sm = 0.f;
                for (int i = 0; i < 128; i++){ SH[i] = expf(SH[i] - mx); sm += SH[i]; }
                SH[128] = 1.0f / sm;
            }
            __syncthreads();
            float inv = SH[128];
            int d = tid & 63, tq = tid >> 6;
            const float* ep = enc + ((size_t)b*Tsz + tq*32)*Hsz + hb + d;
            float part = 0.f;
            #pragma unroll 8
            for (int i = 0; i < 32; i++)
                part += SH[tq*32 + i] * __ldg(ep + (size_t)i*Hsz);
            SH[256 + tq*64 + d] = part;
            __syncthreads();
            if (tid < 64){
                float v = (SH[256+tid] + SH[320+tid] + SH[384+tid] + SH[448+tid]) * inv;
                __stcg(g_ctxT + (hb + tid)*16 + b, v);
            }
        }
        gbar(++p);

        /* ---- phase D: gic (ctx part of gates) + GRU update ---- */
        stageSH(SH, g_ctxT);
        {
            int j = wg >> 1, bh = (wg & 1)*8;
            float a0[8], a1[8], a2[8];
            #pragma unroll
            for (int b = 0; b < 8; b++){ a0[b]=0.f; a1[b]=0.f; a2[b]=0.f; }
            const float* wr = Wih + (size_t)j*1024 + 512;
            const float* wz = Wih + (size_t)(j+512)*1024 + 512;
            const float* wn = Wih + (size_t)(j+1024)*1024 + 512;
            #pragma unroll 4
            for (int ki = 0; ki < 16; ki++){
                int k = ki*32 + lane;
                float r_ = __ldg(wr + k), z_ = __ldg(wz + k), n_ = __ldg(wn + k);
                #pragma unroll
                for (int b = 0; b < 8; b++){
                    float c = SH[k*17 + bh + b];
                    a0[b] = fmaf(r_, c, a0[b]);
                    a1[b] = fmaf(z_, c, a1[b]);
                    a2[b] = fmaf(n_, c, a2[b]);
                }
            }
            #pragma unroll
            for (int b = 0; b < 8; b++){
                float v0 = wred(a0[b]);
                float v1 = wred(a1[b]);
                float v2 = wred(a2[b]);
                if (lane == b){
                    int bb = bh + b;
                    size_t m = (size_t)s*16 + bb;
                    float gir = __ldg(g_gix + m*1536 + j)        + v0;
                    float giz = __ldg(g_gix + m*1536 + 512 + j)  + v1;
                    float gin = __ldg(g_gix + m*1536 + 1024 + j) + v2;
                    float ghr = __ldcg(g_gh + bb*1536 + j);
                    float ghz = __ldcg(g_gh + bb*1536 + 512 + j);
                    float ghn = __ldcg(g_gh + bb*1536 + 1024 + j);
                    float hp  = __ldcg(g_hT + (s&1)*(Hsz*Bsz) + j*16 + bb);
                    float rr = sigf(gir + ghr);
                    float zz = sigf(giz + ghz);
                    float nn = tanhf(gin + rr*ghn);
                    float hN = (1.0f - zz)*nn + zz*hp;
                    __stcg(g_Hs + m*Hsz + j, hN);
                    __stcg(g_hT + ((s+1)&1)*(Hsz*Bsz) + j*16 + bb, hN);
                }
            }
        }
        gbar(++p);
    }
}

/* ---------- launch ---------- */
extern "C" void kernel_launch(void* const* d_in, const int* in_sizes, int n_in,
                              void* d_out, int out_size)
{
    const float* enc  = (const float*)d_in[0];
    const float* eh   = (const float*)d_in[1];
    const int*   msk  = (const int*)  d_in[2];
    const int*   tgt  = (const int*)  d_in[3];
    const float* emb  = (const float*)d_in[4];
    const float* Wq   = (const float*)d_in[5];
    const float* bq   = (const float*)d_in[6];
    const float* Wv   = (const float*)d_in[7];
    const float* bv   = (const float*)d_in[8];
    const float* Wc   = (const float*)d_in[9];
    const float* bc   = (const float*)d_in[10];
    const float* Wih  = (const float*)d_in[11];
    const float* Whh  = (const float*)d_in[12];
    const float* bih  = (const float*)d_in[13];
    const float* bhh  = (const float*)d_in[14];
    const float* Wo   = (const float*)d_in[15];
    const float* bo   = (const float*)d_in[16];
    float* out = (float*)d_out;

    float *p_vt, *p_xe, *p_gix, *p_Hs;
    cudaGetSymbolAddress((void**)&p_vt,  g_vt);
    cudaGetSymbolAddress((void**)&p_xe,  g_xe);
    cudaGetSymbolAddress((void**)&p_gix, g_gix);
    cudaGetSymbolAddress((void**)&p_Hs,  g_Hs);

    k_h0<<<32, 256>>>(eh);
    k_gather<<<MR, 256>>>(emb, tgt);
    /* vt = enc @ Wv^T + bv : M=2048 N=512 */
    k_gemm128<false><<<dim3(4,16), 256>>>(enc, Wv, bv, p_vt, Bsz*Tsz, 512, 512);
    /* gix = xe @ Wih[:, :H]^T + bih : M=2032 N=1536 (ldb = 2H = 1024) */
    k_gemm128<false><<<dim3(12,16), 256>>>(p_xe, Wih, bih, p_gix, MR, 1024, 1536);
    k_zero<<<2000, 256>>>(out);
    k_recur<<<NB, 256>>>(enc, msk, Wq, bq, Whh, bhh, Wih, Wc, bc);
    /* logits = Hs @ Wo^T + bo, scattered into out[b, s+1, :] : M=2032 N=32000 */
    k_gemm128<true><<<dim3(250,16), 256>>>(p_Hs, Wo, bo, out, MR, 512, 0);
    if (out_size >= Bsz*Tsz*Vsz + Bsz*Hsz)
        k_tail<<<32, 256>>>(out);
}

// round 6
// speedup vs baseline: 1.0592x; 1.0592x over previous
#include <cuda_runtime.h>
#include <math.h>
#include <float.h>

#define Bsz 16
#define Tsz 128
#define Hsz 512
#define Vsz 32000
#define STEPS 127
#define MR (STEPS*Bsz)   /* 2032 */
#define NB 128

/* ---------- device scratch ---------- */
__device__ float g_vt[Bsz*Tsz*Hsz];
__device__ float g_xe[MR*Hsz];
__device__ float g_gix[MR*3*Hsz];
__device__ float g_Hs[MR*Hsz];
__device__ float g_q[Bsz*Hsz];
__device__ float g_gh[Bsz*3*Hsz];
__device__ float g_scores[Bsz*Tsz];
__device__ float g_ctxT[Hsz*Bsz];
__device__ float g_hT[2*Hsz*Bsz];
__device__ volatile int g_flags[NB];
__device__ volatile int g_rel;

/* ---------- helpers ---------- */
__device__ __forceinline__ unsigned long long pk2(float lo, float hi){
    unsigned long long r; asm("mov.b64 %0,{%1,%2};" : "=l"(r) : "f"(lo), "f"(hi)); return r;
}
__device__ __forceinline__ void upk2(unsigned long long v, float& lo, float& hi){
    asm("mov.b64 {%0,%1},%2;" : "=f"(lo), "=f"(hi) : "l"(v));
}
__device__ __forceinline__ void fma2(unsigned long long& d, unsigned long long a, unsigned long long b){
    asm("fma.rn.f32x2 %0,%1,%2,%0;" : "+l"(d) : "l"(a), "l"(b));
}
__device__ __forceinline__ float wred(float v){
    v += __shfl_xor_sync(0xffffffffu, v, 16);
    v += __shfl_xor_sync(0xffffffffu, v, 8);
    v += __shfl_xor_sync(0xffffffffu, v, 4);
    v += __shfl_xor_sync(0xffffffffu, v, 2);
    v += __shfl_xor_sync(0xffffffffu, v, 1);
    return v;
}
__device__ __forceinline__ float wmax(float v){
    v = fmaxf(v, __shfl_xor_sync(0xffffffffu, v, 16));
    v = fmaxf(v, __shfl_xor_sync(0xffffffffu, v, 8));
    v = fmaxf(v, __shfl_xor_sync(0xffffffffu, v, 4));
    v = fmaxf(v, __shfl_xor_sync(0xffffffffu, v, 2));
    v = fmaxf(v, __shfl_xor_sync(0xffffffffu, v, 1));
    return v;
}
/* fast tanh/sigmoid via MUFU (__expf + __fdividef); |err| ~1e-6 */
__device__ __forceinline__ float ftanh(float x){
    float cx = fminf(fmaxf(x, -9.f), 9.f);
    float e = __expf(2.f*cx);
    return __fdividef(e - 1.f, e + 1.f);
}
__device__ __forceinline__ float fsig(float x){
    float cx = fminf(fmaxf(x, -30.f), 30.f);
    return __fdividef(1.f, 1.f + __expf(-cx));
}

/* ---------- init: h0 transpose + barrier reset ---------- */
__global__ void k_h0(const float* __restrict__ eh){
    int i = blockIdx.x*256 + threadIdx.x;           /* 8192 */
    if (i < Hsz*Bsz){
        int b = i >> 9, k = i & 511;
        g_hT[k*16 + b] = eh[i];
    }
    if (blockIdx.x == 0 && threadIdx.x < NB) g_flags[threadIdx.x] = 0;
    if (blockIdx.x == 0 && threadIdx.x == 0) g_rel = 0;
}

/* ---------- gather embeddings ---------- */
__global__ void k_gather(const float* __restrict__ emb, const int* __restrict__ tgt){
    int m = blockIdx.x;                 /* 0..2031, m = s*16+b */
    int s = m >> 4, b = m & 15;
    int tok = (s == 0) ? 1 : tgt[b*Tsz + s];
    const float4* src = (const float4*)(emb + (size_t)tok*Hsz);
    float4* dst = (float4*)(g_xe + (size_t)m*Hsz);
    for (int i = threadIdx.x; i < Hsz/4; i += blockDim.x) dst[i] = src[i];
}

/* ---------- zero out[:,0,:] ---------- */
__global__ void k_zero(float* __restrict__ out){
    int i = blockIdx.x*256 + threadIdx.x;           /* 512000 */
    int b = i / Vsz, v = i - b*Vsz;
    out[(size_t)b*Tsz*Vsz + v] = 0.0f;
}

/* ---------- hT tail ---------- */
__global__ void k_tail(float* __restrict__ out){
    int i = blockIdx.x*256 + threadIdx.x;           /* 8192 */
    int b = i >> 9, k = i & 511;
    out[(size_t)Bsz*Tsz*Vsz + i] = g_Hs[(size_t)((STEPS-1)*16 + b)*Hsz + k];
}

/* ---------- 128x128 fp32 GEMM: C = A @ B^T + bias (FFMA2, double-buffered) ----------
   grid.x = M blocks (so all M-blocks of an N stripe co-resident -> B reused via L2),
   grid.y = N blocks. */
template<bool SCATTER>
__global__ void __launch_bounds__(256, 2)
k_gemm128(const float* __restrict__ A, const float* __restrict__ B,
          const float* __restrict__ bias, float* __restrict__ C,
          int M, int ldb, int ldc)
{
    __shared__ float As[2][16][136];
    __shared__ float Bs[2][16][136];
    int tid = threadIdx.x;
    int tx = tid & 15, ty = tid >> 4;
    int m0 = blockIdx.x*128, n0 = blockIdx.y*128;
    int lr = tid >> 1, lq = (tid & 1)*8;

    unsigned long long acc[8][4];
    #pragma unroll
    for (int i = 0; i < 8; i++){
        #pragma unroll
        for (int j = 0; j < 4; j++) acc[i][j] = 0ull;
    }

    bool av = (m0 + lr) < M;
    const float* Arow = A + (size_t)(m0 + lr)*512 + lq;
    const float* Brow = B + (size_t)(n0 + lr)*ldb + lq;

    /* prologue: tile 0 */
    {
        float4 a0, a1, b0, b1;
        if (av){ a0 = *(const float4*)(Arow); a1 = *(const float4*)(Arow + 4); }
        else   { a0 = make_float4(0,0,0,0); a1 = a0; }
        b0 = *(const float4*)(Brow);
        b1 = *(const float4*)(Brow + 4);
        As[0][lq+0][lr]=a0.x; As[0][lq+1][lr]=a0.y; As[0][lq+2][lr]=a0.z; As[0][lq+3][lr]=a0.w;
        As[0][lq+4][lr]=a1.x; As[0][lq+5][lr]=a1.y; As[0][lq+6][lr]=a1.z; As[0][lq+7][lr]=a1.w;
        Bs[0][lq+0][lr]=b0.x; Bs[0][lq+1][lr]=b0.y; Bs[0][lq+2][lr]=b0.z; Bs[0][lq+3][lr]=b0.w;
        Bs[0][lq+4][lr]=b1.x; Bs[0][lq+5][lr]=b1.y; Bs[0][lq+6][lr]=b1.z; Bs[0][lq+7][lr]=b1.w;
    }
    __syncthreads();

    int cur = 0;
    for (int t = 0; t < 32; t++){
        float4 na0, na1, nb0, nb1;
        if (t < 31){
            int k0 = (t+1)*16;
            if (av){ na0 = *(const float4*)(Arow + k0); na1 = *(const float4*)(Arow + k0 + 4); }
            else   { na0 = make_float4(0,0,0,0); na1 = na0; }
            nb0 = *(const float4*)(Brow + k0);
            nb1 = *(const float4*)(Brow + k0 + 4);
        }
        #pragma unroll
        for (int kk = 0; kk < 16; kk++){
            float4 aA = *(const float4*)&As[cur][kk][ty*8];
            float4 aB = *(const float4*)&As[cur][kk][ty*8 + 4];
            ulonglong2 bp0 = *(const ulonglong2*)&Bs[cur][kk][tx*8];
            ulonglong2 bp1 = *(const ulonglong2*)&Bs[cur][kk][tx*8 + 4];
            float am[8] = {aA.x,aA.y,aA.z,aA.w,aB.x,aB.y,aB.z,aB.w};
            #pragma unroll
            for (int i = 0; i < 8; i++){
                unsigned long long ad = pk2(am[i], am[i]);
                fma2(acc[i][0], ad, bp0.x);
                fma2(acc[i][1], ad, bp0.y);
                fma2(acc[i][2], ad, bp1.x);
                fma2(acc[i][3], ad, bp1.y);
            }
        }
        if (t < 31){
            int nx = cur ^ 1;
            As[nx][lq+0][lr]=na0.x; As[nx][lq+1][lr]=na0.y; As[nx][lq+2][lr]=na0.z; As[nx][lq+3][lr]=na0.w;
            As[nx][lq+4][lr]=na1.x; As[nx][lq+5][lr]=na1.y; As[nx][lq+6][lr]=na1.z; As[nx][lq+7][lr]=na1.w;
            Bs[nx][lq+0][lr]=nb0.x; Bs[nx][lq+1][lr]=nb0.y; Bs[nx][lq+2][lr]=nb0.z; Bs[nx][lq+3][lr]=nb0.w;
            Bs[nx][lq+4][lr]=nb1.x; Bs[nx][lq+5][lr]=nb1.y; Bs[nx][lq+6][lr]=nb1.z; Bs[nx][lq+7][lr]=nb1.w;
        }
        __syncthreads();
        cur ^= 1;
    }

    float bb[8];
    #pragma unroll
    for (int c = 0; c < 8; c++) bb[c] = __ldg(bias + n0 + tx*8 + c);

    #pragma unroll
    for (int i = 0; i < 8; i++){
        int row = m0 + ty*8 + i;
        if (row < M){
            float* dst;
            if (SCATTER){
                int b = row & 15, s = row >> 4;
                dst = C + (size_t)b*Tsz*Vsz + (size_t)(s+1)*Vsz + n0 + tx*8;
            } else {
                dst = C + (size_t)row*ldc + n0 + tx*8;
            }
            float4 r0, r1;
            upk2(acc[i][0], r0.x, r0.y); upk2(acc[i][1], r0.z, r0.w);
            upk2(acc[i][2], r1.x, r1.y); upk2(acc[i][3], r1.z, r1.w);
            r0.x += bb[0]; r0.y += bb[1]; r0.z += bb[2]; r0.w += bb[3];
            r1.x += bb[4]; r1.y += bb[5]; r1.z += bb[6]; r1.w += bb[7];
            *(float4*)dst = r0; *(float4*)(dst+4) = r1;
        }
    }
}

/* ---------- persistent recurrence ---------- */
__device__ __forceinline__ void gbar(int p){
    __syncthreads();
    if (blockIdx.x == 0 && threadIdx.x < 32){
        if (threadIdx.x == 0){ __threadfence(); g_flags[0] = p; }
        for (int i = threadIdx.x; i < NB; i += 32){ while (g_flags[i] < p) {} }
        __syncwarp();
        if (threadIdx.x == 0){ __threadfence(); g_rel = p; }
    } else if (threadIdx.x == 0){
        __threadfence();
        g_flags[blockIdx.x] = p;
        while (g_rel < p) {}
        __threadfence();
    }
    __syncthreads();
}

__device__ __forceinline__ void stageSH(float* SH, const float* src){
    __syncthreads();
    for (int i = threadIdx.x; i < Hsz*Bsz; i += 256)
        SH[(i>>4)*17 + (i&15)] = __ldcg(src + i);
    __syncthreads();
}

/* warp: 2 rows x 16 batches, K=512; SH = rhs [k][b] pad17 */
__device__ __forceinline__ void bgemm2(const float* __restrict__ w0r, const float* __restrict__ w1r,
                                       float bias0, float bias1,
                                       float* o0, float* o1, int st,
                                       const float* SH, int lane)
{
    float a0[16], a1[16];
    #pragma unroll
    for (int b = 0; b < 16; b++){ a0[b]=0.f; a1[b]=0.f; }
    #pragma unroll 8
    for (int ki = 0; ki < 16; ki++){
        int k = ki*32 + lane;
        float w0 = __ldg(w0r + k), w1 = __ldg(w1r + k);
        #pragma unroll
        for (int b = 0; b < 16; b++){
            float hv = SH[k*17 + b];
            a0[b] = fmaf(w0, hv, a0[b]);
            a1[b] = fmaf(w1, hv, a1[b]);
        }
    }
    #pragma unroll
    for (int b = 0; b < 16; b++){
        float v0 = wred(a0[b]);
        float v1 = wred(a1[b]);
        if (lane == b){
            __stcg(o0 + b*st, v0 + bias0);
            __stcg(o1 + b*st, v1 + bias1);
        }
    }
}

__global__ void __launch_bounds__(256)
k_recur(const float* __restrict__ enc, const int* __restrict__ mask,
        const float* __restrict__ Wq,  const float* __restrict__ bq,
        const float* __restrict__ Whh, const float* __restrict__ bhh,
        const float* __restrict__ Wih, const float* __restrict__ Wc,
        const float* __restrict__ bc)
{
    __shared__ float SH[Hsz*17];
    int tid = threadIdx.x;
    int lane = tid & 31;
    int wg = blockIdx.x*8 + (tid >> 5);        /* 0..1023 */
    float bcv = __ldg(bc);
    int p = 0;

    for (int s = 0; s < STEPS; s++){
        /* ---- phase A: q = h@Wq^T+bq ; gh = h@Whh^T+bhh ---- */
        stageSH(SH, g_hT + (s&1)*(Hsz*Bsz));
        {
            int r0 = 2*wg;
            if (r0 < 512){
                bgemm2(Wq + (size_t)r0*512, Wq + (size_t)(r0+1)*512,
                       __ldg(bq+r0), __ldg(bq+r0+1),
                       g_q + r0, g_q + r0 + 1, 512, SH, lane);
            } else {
                int g = r0 - 512;
                bgemm2(Whh + (size_t)g*512, Whh + (size_t)(g+1)*512,
                       __ldg(bhh+g), __ldg(bhh+g+1),
                       g_gh + g, g_gh + g + 1, 1536, SH, lane);
            }
        }
        gbar(++p);

        /* ---- phase B: scores (warp = 2 (b,t) rows, MLP-16 loads, fast tanh) ---- */
        {
            int pr0 = 2*wg;
            int b = pr0 >> 7, t0 = pr0 & 127;
            const float* qp = g_q + b*Hsz;
            float qk[16], wv[16];
            #pragma unroll
            for (int ki = 0; ki < 16; ki++){
                int k = ki*32 + lane;
                qk[ki] = __ldcg(qp + k);
                wv[ki] = __ldg(Wc + k);
            }
            #pragma unroll
            for (int i = 0; i < 2; i++){
                int t = t0 + i;
                const float* vp = g_vt + ((size_t)b*Tsz + t)*Hsz;
                float vv[16];
                #pragma unroll
                for (int ki = 0; ki < 16; ki++) vv[ki] = __ldg(vp + ki*32 + lane);
                float acc = 0.f;
                #pragma unroll
                for (int ki = 0; ki < 16; ki++) acc += wv[ki] * ftanh(qk[ki] + vv[ki]);
                acc = wred(acc);
                if (lane == 0){
                    float sc = acc + bcv;
                    if (__ldg(mask + b*Tsz + t) == 0) sc = -FLT_MAX;
                    __stcg(g_scores + b*Tsz + t, sc);
                }
            }
        }
        gbar(++p);

        /* ---- phase C: softmax (parallel) + ctx (CTA = (b, 64-dim chunk)) ---- */
        {
            int b = blockIdx.x >> 3, ch = blockIdx.x & 7, hb = ch*64;
            __syncthreads();
            float sv = -FLT_MAX;
            if (tid < 128){
                sv = __ldcg(g_scores + b*Tsz + tid);
                float m = wmax(sv);
                if (lane == 0) SH[140 + (tid>>5)] = m;
            }
            __syncthreads();
            if (tid == 0)
                SH[148] = fmaxf(fmaxf(SH[140],SH[141]), fmaxf(SH[142],SH[143]));
            __syncthreads();
            if (tid < 128){
                float e = __expf(sv - SH[148]);
                SH[tid] = e;
                float sm = wred(e);
                if (lane == 0) SH[152 + (tid>>5)] = sm;
            }
            __syncthreads();
            if (tid == 0)
                SH[128] = __fdividef(1.f, SH[152]+SH[153]+SH[154]+SH[155]);
            __syncthreads();
            float inv = SH[128];
            int d = tid & 63, tq = tid >> 6;
            const float* ep = enc + ((size_t)b*Tsz + tq*32)*Hsz + hb + d;
            float part = 0.f;
            #pragma unroll 8
            for (int i = 0; i < 32; i++)
                part += SH[tq*32 + i] * __ldg(ep + (size_t)i*Hsz);
            SH[256 + tq*64 + d] = part;
            __syncthreads();
            if (tid < 64){
                float v = (SH[256+tid] + SH[320+tid] + SH[384+tid] + SH[448+tid]) * inv;
                __stcg(g_ctxT + (hb + tid)*16 + b, v);
            }
        }
        gbar(++p);

        /* ---- phase D: gic (ctx part of gates) + GRU update ---- */
        stageSH(SH, g_ctxT);
        {
            int j = wg >> 1, bh = (wg & 1)*8;
            float a0[8], a1[8], a2[8];
            #pragma unroll
            for (int b = 0; b < 8; b++){ a0[b]=0.f; a1[b]=0.f; a2[b]=0.f; }
            const float* wr = Wih + (size_t)j*1024 + 512;
            const float* wz = Wih + (size_t)(j+512)*1024 + 512;
            const float* wn = Wih + (size_t)(j+1024)*1024 + 512;
            #pragma unroll 8
            for (int ki = 0; ki < 16; ki++){
                int k = ki*32 + lane;
                float r_ = __ldg(wr + k), z_ = __ldg(wz + k), n_ = __ldg(wn + k);
                #pragma unroll
                for (int b = 0; b < 8; b++){
                    float c = SH[k*17 + bh + b];
                    a0[b] = fmaf(r_, c, a0[b]);
                    a1[b] = fmaf(z_, c, a1[b]);
                    a2[b] = fmaf(n_, c, a2[b]);
                }
            }
            #pragma unroll
            for (int b = 0; b < 8; b++){
                float v0 = wred(a0[b]);
                float v1 = wred(a1[b]);
                float v2 = wred(a2[b]);
                if (lane == b){
                    int bb = bh + b;
                    size_t m = (size_t)s*16 + bb;
                    float gir = __ldg(g_gix + m*1536 + j)        + v0;
                    float giz = __ldg(g_gix + m*1536 + 512 + j)  + v1;
                    float gin = __ldg(g_gix + m*1536 + 1024 + j) + v2;
                    float ghr = __ldcg(g_gh + bb*1536 + j);
                    float ghz = __ldcg(g_gh + bb*1536 + 512 + j);
                    float ghn = __ldcg(g_gh + bb*1536 + 1024 + j);
                    float hp  = __ldcg(g_hT + (s&1)*(Hsz*Bsz) + j*16 + bb);
                    float rr = fsig(gir + ghr);
                    float zz = fsig(giz + ghz);
                    float nn = ftanh(gin + rr*ghn);
                    float hN = (1.0f - zz)*nn + zz*hp;
                    __stcg(g_Hs + m*Hsz + j, hN);
                    __stcg(g_hT + ((s+1)&1)*(Hsz*Bsz) + j*16 + bb, hN);
                }
            }
        }
        gbar(++p);
    }
}

/* ---------- launch ---------- */
extern "C" void kernel_launch(void* const* d_in, const int* in_sizes, int n_in,
                              void* d_out, int out_size)
{
    const float* enc  = (const float*)d_in[0];
    const float* eh   = (const float*)d_in[1];
    const int*   msk  = (const int*)  d_in[2];
    const int*   tgt  = (const int*)  d_in[3];
    const float* emb  = (const float*)d_in[4];
    const float* Wq   = (const float*)d_in[5];
    const float* bq   = (const float*)d_in[6];
    const float* Wv   = (const float*)d_in[7];
    const float* bv   = (const float*)d_in[8];
    const float* Wc   = (const float*)d_in[9];
    const float* bc   = (const float*)d_in[10];
    const float* Wih  = (const float*)d_in[11];
    const float* Whh  = (const float*)d_in[12];
    const float* bih  = (const float*)d_in[13];
    const float* bhh  = (const float*)d_in[14];
    const float* Wo   = (const float*)d_in[15];
    const float* bo   = (const float*)d_in[16];
    float* out = (float*)d_out;

    float *p_vt, *p_xe, *p_gix, *p_Hs;
    cudaGetSymbolAddress((void**)&p_vt,  g_vt);
    cudaGetSymbolAddress((void**)&p_xe,  g_xe);
    cudaGetSymbolAddress((void**)&p_gix, g_gix);
    cudaGetSymbolAddress((void**)&p_Hs,  g_Hs);

    k_h0<<<32, 256>>>(eh);
    k_gather<<<MR, 256>>>(emb, tgt);
    /* vt = enc @ Wv^T + bv : M=2048 N=512  (grid = Mblk x Nblk) */
    k_gemm128<false><<<dim3(16,4), 256>>>(enc, Wv, bv, p_vt, Bsz*Tsz, 512, 512);
    /* gix = xe @ Wih[:, :H]^T + bih : M=2032 N=1536 (ldb = 2H = 1024) */
    k_gemm128<false><<<dim3(16,12), 256>>>(p_xe, Wih, bih, p_gix, MR, 1024, 1536);
    k_zero<<<2000, 256>>>(out);
    k_recur<<<NB, 256>>>(enc, msk, Wq, bq, Whh, bhh, Wih, Wc, bc);
    /* logits = Hs @ Wo^T + bo, scattered into out[b, s+1, :] : M=2032 N=32000 */
    k_gemm128<true><<<dim3(16,250), 256>>>(p_Hs, Wo, bo, out, MR, 512, 0);
    if (out_size >= Bsz*Tsz*Vsz + Bsz*Hsz)
        k_tail<<<32, 256>>>(out);
}